// round 7
// baseline (speedup 1.0000x reference)
#include <cuda_runtime.h>
#include <cuda_bf16.h>
#include <math.h>
#include <stdint.h>

#define NN   50000
#define NE   800000
#define D    128
#define DOUT 40
#define NBLK ((NN + 255) / 256)   // 196

// scratch (allocation-free rule: __device__ globals)
__device__ float g_h1[NN * D];
__device__ float g_h2[NN * D];
__device__ float g_dinv[NN];
__device__ int   g_cnt[NN];
__device__ int   g_rowptr[NN];
__device__ int   g_cursor[NN];
__device__ int   g_bsum[256];
__device__ int   g_csr[NE];
__device__ int   g_is64;

// ---------------------------------------------------------------------------
// init: zero counts; block 0 also detects edge_index dtype (int32 vs int64)
__global__ void k_init(const int* __restrict__ ei32) {
    int i = blockIdx.x * 256 + threadIdx.x;
    if (i < NN) g_cnt[i] = 0;
    if (blockIdx.x == 0) {
        int nz = (ei32[2 * threadIdx.x + 1] != 0) ? 1 : 0;
        int cnt_nz = __syncthreads_count(nz);
        if (threadIdx.x == 0) g_is64 = (cnt_nz == 0) ? 1 : 0;
    }
}

__device__ __forceinline__ int edge_val(const void* ei, long long idx, int is64) {
    if (is64) return (int)((const long long*)ei)[idx];
    return ((const int*)ei)[idx];
}

__global__ void __launch_bounds__(256) k_hist(const void* __restrict__ ei) {
    int e = blockIdx.x * blockDim.x + threadIdx.x;
    if (e >= NE) return;
    int is64 = g_is64;
    int d = edge_val(ei, (long long)NE + e, is64);
    atomicAdd(&g_cnt[d], 1);
}

__global__ void __launch_bounds__(256) k_scanA() {
    __shared__ int sb[256];
    int t = threadIdx.x;
    int i = blockIdx.x * 256 + t;
    int v = (i < NN) ? g_cnt[i] : 0;
    sb[t] = v;
    __syncthreads();
    for (int off = 1; off < 256; off <<= 1) {
        int tv = (t >= off) ? sb[t - off] : 0;
        __syncthreads();
        sb[t] += tv;
        __syncthreads();
    }
    int incl = sb[t];
    if (i < NN) g_rowptr[i] = incl - v;
    if (t == 255) g_bsum[blockIdx.x] = incl;
}

__global__ void __launch_bounds__(256) k_scanB() {
    __shared__ int sb[256];
    int t = threadIdx.x;
    int v = (t < NBLK) ? g_bsum[t] : 0;
    sb[t] = v;
    __syncthreads();
    for (int off = 1; off < 256; off <<= 1) {
        int tv = (t >= off) ? sb[t - off] : 0;
        __syncthreads();
        sb[t] += tv;
        __syncthreads();
    }
    if (t < NBLK) g_bsum[t] = sb[t] - v;
}

__global__ void __launch_bounds__(256) k_scanC() {
    int i = blockIdx.x * 256 + threadIdx.x;
    if (i < NN) {
        int rp = g_rowptr[i] + g_bsum[blockIdx.x];
        g_rowptr[i] = rp;
        g_cursor[i] = rp;
        g_dinv[i] = 1.0f / (float)max(g_cnt[i], 1);
    }
}

__global__ void __launch_bounds__(256) k_fill(const void* __restrict__ ei) {
    int e = blockIdx.x * blockDim.x + threadIdx.x;
    if (e >= NE) return;
    int is64 = g_is64;
    int s = edge_val(ei, e, is64);
    int d = edge_val(ei, (long long)NE + e, is64);
    int pos = atomicAdd(&g_cursor[d], 1);
    g_csr[pos] = s;
}

// ---------------------------------------------------------------------------
// common MMA helpers
__device__ __forceinline__ uint32_t smem_u32(const void* p) {
    uint32_t a;
    asm("{ .reg .u64 t; cvta.to.shared.u64 t, %1; cvt.u32.u64 %0, t; }"
        : "=r"(a) : "l"(p));
    return a;
}

__device__ __forceinline__ void ldm_x4(uint32_t addr, uint32_t* r) {
    asm volatile("ldmatrix.sync.aligned.m8n8.x4.shared.b16 {%0,%1,%2,%3}, [%4];"
                 : "=r"(r[0]), "=r"(r[1]), "=r"(r[2]), "=r"(r[3]) : "r"(addr));
}

__device__ __forceinline__ void mma_bf16(float* d, const uint32_t* a,
                                         const uint32_t* b) {
    asm volatile(
        "mma.sync.aligned.m16n8k16.row.col.f32.bf16.bf16.f32 "
        "{%0,%1,%2,%3}, {%4,%5,%6,%7}, {%8,%9}, {%0,%1,%2,%3};"
        : "+f"(d[0]), "+f"(d[1]), "+f"(d[2]), "+f"(d[3])
        : "r"(a[0]), "r"(a[1]), "r"(a[2]), "r"(a[3]), "r"(b[0]), "r"(b[1]));
}

__device__ __forceinline__ void cvt_pair(float x0, float x1, uint32_t& hi,
                                         uint32_t& lo) {
    __nv_bfloat16 h0 = __float2bfloat16(x0);
    __nv_bfloat16 h1 = __float2bfloat16(x1);
    float r0 = x0 - __bfloat162float(h0);
    float r1 = x1 - __bfloat162float(h1);
    __nv_bfloat162 hp(h0, h1);
    __nv_bfloat162 lp(__float2bfloat16(r0), __float2bfloat16(r1));
    hi = *reinterpret_cast<uint32_t*>(&hp);
    lo = *reinterpret_cast<uint32_t*>(&lp);
}

// ---------------------------------------------------------------------------
// fused gather-agg + mma.sync bf16 layer (hi/lo split, 3 passes). 512 threads.
// Per 128-node tile:
//   phase A (half0): warps gather-aggregate neighbor means from CSR -> sA bf16
//   phase B (half1): convert xin rows -> sA bf16
//   MMA: D[128,128] += A_half @ W_half^T, fp32 accum
#define TILES_PER_BLK 3
#define NTILES ((NN + 127) / 128)                               // 391
#define MMA_GRID ((NTILES + TILES_PER_BLK - 1) / TILES_PER_BLK) // 131

#define SB_OFF   0
#define A_HI_OFF 1024
#define A_LO_OFF (A_HI_OFF + 34816)       // 128 rows * 272B
#define B_HI_OFF (A_LO_OFF + 34816)       // 70656
#define B_LO_OFF (B_HI_OFF + 67584)       // 128 rows * 528B
#define SMEM_MMA_BYTES (B_LO_OFF + 67584) // 205824
#define RSA 272
#define RSB 528

__global__ void __launch_bounds__(512, 1) k_layer_fused(const float* __restrict__ xin_param,
                                                        const float* __restrict__ Wl,
                                                        const float* __restrict__ Wr,
                                                        const float* __restrict__ b,
                                                        int first) {
    extern __shared__ char smem[];
    uint32_t sbase = smem_u32(smem);
    float* sbias = (float*)(smem + SB_OFF);

    const float* xin = first ? xin_param : g_h1;
    const float* feat = xin;             // gather source = layer input
    float* hout = first ? g_h1 : g_h2;

    int tid = threadIdx.x;
    int lane = tid & 31;
    int wid = tid >> 5;
    int wm = wid >> 2;       // 0..3 -> m offset wm*32
    int wn = wid & 3;        // 0..3 -> n offset wn*32

    if (tid < 128) sbias[tid] = b[tid];

    // convert weights once: [o][k] hi/lo bf16, padded rows
    for (int i = 0; i < 32; i++) {
        int p = tid + i * 512;          // 0..16383
        int o = p >> 7;
        int kp = p & 127;
        float2 v = (kp < 64) ? *(const float2*)(Wl + o * 128 + kp * 2)
                             : *(const float2*)(Wr + o * 128 + (kp - 64) * 2);
        uint32_t hi, lo;
        cvt_pair(v.x, v.y, hi, lo);
        *(uint32_t*)(smem + B_HI_OFF + o * RSB + kp * 4) = hi;
        *(uint32_t*)(smem + B_LO_OFF + o * RSB + kp * 4) = lo;
    }
    __syncthreads();

    int sub = lane >> 3;
    int rin = lane & 7;
    int a_row = (sub & 1) * 8 + rin;
    int a_kof = (sub >> 1) * 8;
    int b_row = (sub >> 1) * 8 + rin;
    int b_kof = (sub & 1) * 8;

    for (int t = 0; t < TILES_PER_BLK; t++) {
        int node0 = (blockIdx.x * TILES_PER_BLK + t) * 128;
        if (node0 >= NN) break;

        float acc[2][4][4];
#pragma unroll
        for (int mt = 0; mt < 2; mt++)
#pragma unroll
            for (int nt = 0; nt < 4; nt++)
#pragma unroll
                for (int j = 0; j < 4; j++) acc[mt][nt][j] = 0.f;

        for (int half = 0; half < 2; half++) {
            if (half == 0) {
                // gather-aggregate: warp w handles rows w, w+16, ..., w+112
#pragma unroll
                for (int it = 0; it < 8; it++) {
                    int r = it * 16 + wid;
                    int node = node0 + r;
                    float4 a0 = make_float4(0.f, 0.f, 0.f, 0.f);
                    float4 a1 = make_float4(0.f, 0.f, 0.f, 0.f);
                    float4 a2 = make_float4(0.f, 0.f, 0.f, 0.f);
                    float4 a3 = make_float4(0.f, 0.f, 0.f, 0.f);
                    float di = 0.f;
                    if (node < NN) {
                        int start = g_rowptr[node];
                        int end = start + g_cnt[node];
                        di = g_dinv[node];
                        int e = start;
                        for (; e + 3 < end; e += 4) {
                            int s0 = g_csr[e];
                            int s1 = g_csr[e + 1];
                            int s2 = g_csr[e + 2];
                            int s3 = g_csr[e + 3];
                            float4 v0 = *((const float4*)(feat + (size_t)s0 * D) + lane);
                            float4 v1 = *((const float4*)(feat + (size_t)s1 * D) + lane);
                            float4 v2 = *((const float4*)(feat + (size_t)s2 * D) + lane);
                            float4 v3 = *((const float4*)(feat + (size_t)s3 * D) + lane);
                            a0.x += v0.x; a0.y += v0.y; a0.z += v0.z; a0.w += v0.w;
                            a1.x += v1.x; a1.y += v1.y; a1.z += v1.z; a1.w += v1.w;
                            a2.x += v2.x; a2.y += v2.y; a2.z += v2.z; a2.w += v2.w;
                            a3.x += v3.x; a3.y += v3.y; a3.z += v3.z; a3.w += v3.w;
                        }
                        for (; e < end; e++) {
                            int s0 = g_csr[e];
                            float4 v0 = *((const float4*)(feat + (size_t)s0 * D) + lane);
                            a0.x += v0.x; a0.y += v0.y; a0.z += v0.z; a0.w += v0.w;
                        }
                    }
                    float4 m;
                    m.x = (a0.x + a1.x + a2.x + a3.x) * di;
                    m.y = (a0.y + a1.y + a2.y + a3.y) * di;
                    m.z = (a0.z + a1.z + a2.z + a3.z) * di;
                    m.w = (a0.w + a1.w + a2.w + a3.w) * di;
                    uint32_t h0, l0, h1, l1;
                    cvt_pair(m.x, m.y, h0, l0);
                    cvt_pair(m.z, m.w, h1, l1);
                    *(uint2*)(smem + A_HI_OFF + r * RSA + lane * 8) = make_uint2(h0, h1);
                    *(uint2*)(smem + A_LO_OFF + r * RSA + lane * 8) = make_uint2(l0, l1);
                }
            } else {
                // convert xin rows
                for (int i = 0; i < 16; i++) {
                    int p = tid + i * 512;       // 0..8191
                    int r = p >> 6;
                    int kp = p & 63;
                    int node = node0 + r;
                    float2 v = make_float2(0.f, 0.f);
                    if (node < NN) v = *(const float2*)(xin + (size_t)node * D + kp * 2);
                    uint32_t hi, lo;
                    cvt_pair(v.x, v.y, hi, lo);
                    *(uint32_t*)(smem + A_HI_OFF + r * RSA + kp * 4) = hi;
                    *(uint32_t*)(smem + A_LO_OFF + r * RSA + kp * 4) = lo;
                }
            }
            __syncthreads();

#pragma unroll
            for (int ks = 0; ks < 8; ks++) {
                int akc = ks * 16 + a_kof;
                int bkc = half * 128 + ks * 16 + b_kof;

                uint32_t ah[2][4], al[2][4];
#pragma unroll
                for (int mt = 0; mt < 2; mt++) {
                    uint32_t ro = (uint32_t)((wm * 32 + mt * 16 + a_row) * RSA + akc * 2);
                    ldm_x4(sbase + A_HI_OFF + ro, ah[mt]);
                    ldm_x4(sbase + A_LO_OFF + ro, al[mt]);
                }
                uint32_t bh[2][4], bl[2][4];
#pragma unroll
                for (int np = 0; np < 2; np++) {
                    uint32_t ro = (uint32_t)((wn * 32 + np * 16 + b_row) * RSB + bkc * 2);
                    ldm_x4(sbase + B_HI_OFF + ro, bh[np]);
                    ldm_x4(sbase + B_LO_OFF + ro, bl[np]);
                }
#pragma unroll
                for (int mt = 0; mt < 2; mt++) {
#pragma unroll
                    for (int nt = 0; nt < 4; nt++) {
                        const uint32_t* Bh = &bh[nt >> 1][(nt & 1) * 2];
                        const uint32_t* Bl = &bl[nt >> 1][(nt & 1) * 2];
                        mma_bf16(acc[mt][nt], ah[mt], Bh);
                        mma_bf16(acc[mt][nt], ah[mt], Bl);
                        mma_bf16(acc[mt][nt], al[mt], Bh);
                    }
                }
            }
            __syncthreads();
        }

        int qr = lane >> 2;
        int qc = (lane & 3) * 2;
#pragma unroll
        for (int mt = 0; mt < 2; mt++) {
            int n0 = node0 + wm * 32 + mt * 16 + qr;
            int n1 = n0 + 8;
#pragma unroll
            for (int nt = 0; nt < 4; nt++) {
                int o = wn * 32 + nt * 8 + qc;
                float b0 = sbias[o], b1 = sbias[o + 1];
                if (n0 < NN) {
                    float2 v;
                    v.x = fmaxf(acc[mt][nt][0] + b0, 0.f);
                    v.y = fmaxf(acc[mt][nt][1] + b1, 0.f);
                    *(float2*)(hout + (size_t)n0 * D + o) = v;
                }
                if (n1 < NN) {
                    float2 v;
                    v.x = fmaxf(acc[mt][nt][2] + b0, 0.f);
                    v.y = fmaxf(acc[mt][nt][3] + b1, 0.f);
                    *(float2*)(hout + (size_t)n1 * D + o) = v;
                }
            }
        }
        __syncthreads();
    }
}

// ---------------------------------------------------------------------------
// final head on MMA: logits = [h1|h2] @ W_lin^T + b_lin ; log_softmax in regs.
#define RSF 528
#define FA_HI 1024
#define FA_LO (FA_HI + 128 * RSF)            // 68608
#define FB_HI (FA_LO + 128 * RSF)            // 136192
#define FB_LO (FB_HI + 48 * RSF)             // 161536
#define SMEM_FIN_BYTES (FB_LO + 48 * RSF)    // 186880

__global__ void __launch_bounds__(256, 1) k_final_mma(const float* __restrict__ Wlin,
                                                      const float* __restrict__ blin,
                                                      float* __restrict__ out) {
    extern __shared__ char smem[];
    uint32_t sbase = smem_u32(smem);
    float* sbias = (float*)(smem + SB_OFF);

    int tid = threadIdx.x;
    int lane = tid & 31;
    int wid = tid >> 5;
    int node0 = blockIdx.x * 128;

    if (tid < 48) sbias[tid] = (tid < DOUT) ? blin[tid] : 0.f;

    for (int i = 0; i < 24; i++) {
        int p = tid + i * 256;          // 0..6143
        int o = p >> 7;
        int kp = p & 127;
        float2 v = make_float2(0.f, 0.f);
        if (o < DOUT) v = *(const float2*)(Wlin + o * 256 + kp * 2);
        uint32_t hi, lo;
        cvt_pair(v.x, v.y, hi, lo);
        *(uint32_t*)(smem + FB_HI + o * RSF + kp * 4) = hi;
        *(uint32_t*)(smem + FB_LO + o * RSF + kp * 4) = lo;
    }

    for (int i = 0; i < 64; i++) {
        int p = tid + i * 256;          // 0..16383
        int r = p >> 7;
        int kp = p & 127;
        int node = node0 + r;
        float2 v = make_float2(0.f, 0.f);
        if (node < NN) {
            const float* src = (kp < 64) ? (g_h1 + (size_t)node * D + kp * 2)
                                         : (g_h2 + (size_t)node * D + (kp - 64) * 2);
            v = *(const float2*)src;
        }
        uint32_t hi, lo;
        cvt_pair(v.x, v.y, hi, lo);
        *(uint32_t*)(smem + FA_HI + r * RSF + kp * 4) = hi;
        *(uint32_t*)(smem + FA_LO + r * RSF + kp * 4) = lo;
    }
    __syncthreads();

    int sub = lane >> 3;
    int rin = lane & 7;
    int a_row = (sub & 1) * 8 + rin;
    int a_kof = (sub >> 1) * 8;
    int b_row = (sub >> 1) * 8 + rin;
    int b_kof = (sub & 1) * 8;

    float acc[5][4];
#pragma unroll
    for (int nt = 0; nt < 5; nt++)
#pragma unroll
        for (int j = 0; j < 4; j++) acc[nt][j] = 0.f;

#pragma unroll
    for (int ks = 0; ks < 16; ks++) {
        uint32_t ah[4], al[4];
        {
            uint32_t ro = (uint32_t)((wid * 16 + a_row) * RSF + (ks * 16 + a_kof) * 2);
            ldm_x4(sbase + FA_HI + ro, ah);
            ldm_x4(sbase + FA_LO + ro, al);
        }
        uint32_t bh[3][4], bl[3][4];
#pragma unroll
        for (int np = 0; np < 3; np++) {
            uint32_t ro = (uint32_t)((np * 16 + b_row) * RSF + (ks * 16 + b_kof) * 2);
            ldm_x4(sbase + FB_HI + ro, bh[np]);
            ldm_x4(sbase + FB_LO + ro, bl[np]);
        }
#pragma unroll
        for (int nt = 0; nt < 5; nt++) {
            const uint32_t* Bh = &bh[nt >> 1][(nt & 1) * 2];
            const uint32_t* Bl = &bl[nt >> 1][(nt & 1) * 2];
            mma_bf16(acc[nt], ah, Bh);
            mma_bf16(acc[nt], ah, Bl);
            mma_bf16(acc[nt], al, Bh);
        }
    }

    int qc = (lane & 3) * 2;
#pragma unroll
    for (int nt = 0; nt < 5; nt++) {
        int o = nt * 8 + qc;
        acc[nt][0] += sbias[o];
        acc[nt][1] += sbias[o + 1];
        acc[nt][2] += sbias[o];
        acc[nt][3] += sbias[o + 1];
    }

    float m0 = -1e30f, m1 = -1e30f;
#pragma unroll
    for (int nt = 0; nt < 5; nt++) {
        m0 = fmaxf(m0, fmaxf(acc[nt][0], acc[nt][1]));
        m1 = fmaxf(m1, fmaxf(acc[nt][2], acc[nt][3]));
    }
#pragma unroll
    for (int d = 1; d <= 2; d <<= 1) {
        m0 = fmaxf(m0, __shfl_xor_sync(0xffffffffu, m0, d));
        m1 = fmaxf(m1, __shfl_xor_sync(0xffffffffu, m1, d));
    }
    float s0 = 0.f, s1 = 0.f;
#pragma unroll
    for (int nt = 0; nt < 5; nt++) {
        s0 += expf(acc[nt][0] - m0) + expf(acc[nt][1] - m0);
        s1 += expf(acc[nt][2] - m1) + expf(acc[nt][3] - m1);
    }
#pragma unroll
    for (int d = 1; d <= 2; d <<= 1) {
        s0 += __shfl_xor_sync(0xffffffffu, s0, d);
        s1 += __shfl_xor_sync(0xffffffffu, s1, d);
    }
    float lse0 = m0 + logf(s0);
    float lse1 = m1 + logf(s1);

    int qr = lane >> 2;
    int r0 = node0 + wid * 16 + qr;
    int r1 = r0 + 8;
#pragma unroll
    for (int nt = 0; nt < 5; nt++) {
        int o = nt * 8 + qc;
        if (r0 < NN) {
            float2 v = make_float2(acc[nt][0] - lse0, acc[nt][1] - lse0);
            *(float2*)(out + (size_t)r0 * DOUT + o) = v;
        }
        if (r1 < NN) {
            float2 v = make_float2(acc[nt][2] - lse1, acc[nt][3] - lse1);
            *(float2*)(out + (size_t)r1 * DOUT + o) = v;
        }
    }
}

// ---------------------------------------------------------------------------
extern "C" void kernel_launch(void* const* d_in, const int* in_sizes, int n_in,
                              void* d_out, int out_size) {
    const float* x    = (const float*)d_in[0];
    const void*  ei   = d_in[1];
    const float* W1l  = (const float*)d_in[2];
    const float* b1   = (const float*)d_in[3];
    const float* W1r  = (const float*)d_in[4];
    const float* W2l  = (const float*)d_in[5];
    const float* b2   = (const float*)d_in[6];
    const float* W2r  = (const float*)d_in[7];
    const float* Wlin = (const float*)d_in[8];
    const float* blin = (const float*)d_in[9];
    float*       out  = (float*)d_out;

    cudaFuncSetAttribute(k_layer_fused, cudaFuncAttributeMaxDynamicSharedMemorySize,
                         SMEM_MMA_BYTES);
    cudaFuncSetAttribute(k_final_mma, cudaFuncAttributeMaxDynamicSharedMemorySize,
                         SMEM_FIN_BYTES);

    const int edge_blocks = (NE + 255) / 256;      // 3125

    // CSR build (once, reused by both layers)
    k_init<<<NBLK, 256>>>((const int*)ei);
    k_hist<<<edge_blocks, 256>>>(ei);
    k_scanA<<<NBLK, 256>>>();
    k_scanB<<<1, 256>>>();
    k_scanC<<<NBLK, 256>>>();
    k_fill<<<edge_blocks, 256>>>(ei);

    // layers (gather fused into MMA kernel)
    k_layer_fused<<<MMA_GRID, 512, SMEM_MMA_BYTES>>>(x, W1l, W1r, b1, 1);
    k_layer_fused<<<MMA_GRID, 512, SMEM_MMA_BYTES>>>(nullptr, W2l, W2r, b2, 0);

    // head
    k_final_mma<<<NTILES, 256, SMEM_FIN_BYTES>>>(Wlin, blin, out);
}

// round 8
// speedup vs baseline: 1.2913x; 1.2913x over previous
#include <cuda_runtime.h>
#include <cuda_bf16.h>
#include <math.h>
#include <stdint.h>

#define NN   50000
#define NE   800000
#define D    128
#define DOUT 40
#define NBLK ((NN + 255) / 256)   // 196

// scratch (allocation-free rule: __device__ globals)
__device__ float g_agg[NN * D];
__device__ float g_h1[NN * D];
__device__ float g_h2[NN * D];
__device__ float g_dinv[NN];
__device__ int   g_cnt[NN];
__device__ int   g_rowptr[NN];
__device__ int   g_cursor[NN];
__device__ int   g_csr[NE];
__device__ int   g_is64;
__device__ int   g_total;

// ---------------------------------------------------------------------------
// init: zero counts; block 0 detects edge_index dtype and zeroes allocator
__global__ void k_init(const int* __restrict__ ei32) {
    int i = blockIdx.x * 256 + threadIdx.x;
    if (i < NN) g_cnt[i] = 0;
    if (blockIdx.x == 0) {
        int nz = (ei32[2 * threadIdx.x + 1] != 0) ? 1 : 0;
        int cnt_nz = __syncthreads_count(nz);
        if (threadIdx.x == 0) {
            g_is64 = (cnt_nz == 0) ? 1 : 0;
            g_total = 0;
        }
    }
}

__device__ __forceinline__ int edge_val(const void* ei, long long idx, int is64) {
    if (is64) return (int)((const long long*)ei)[idx];
    return ((const int*)ei)[idx];
}

__global__ void __launch_bounds__(256) k_hist(const void* __restrict__ ei) {
    int e = blockIdx.x * blockDim.x + threadIdx.x;
    if (e >= NE) return;
    int is64 = g_is64;
    int d = edge_val(ei, (long long)NE + e, is64);
    atomicAdd(&g_cnt[d], 1);
}

// order-free CSR slot allocation: any disjoint partition of [0, NE) works
__global__ void __launch_bounds__(256) k_alloc() {
    int i = blockIdx.x * 256 + threadIdx.x;
    if (i < NN) {
        int c = g_cnt[i];
        int rp = atomicAdd(&g_total, c);
        g_rowptr[i] = rp;
        g_cursor[i] = rp;
        g_dinv[i] = 1.0f / (float)max(c, 1);
    }
}

__global__ void __launch_bounds__(256) k_fill(const void* __restrict__ ei) {
    int e = blockIdx.x * blockDim.x + threadIdx.x;
    if (e >= NE) return;
    int is64 = g_is64;
    int s = edge_val(ei, e, is64);
    int d = edge_val(ei, (long long)NE + e, is64);
    int pos = atomicAdd(&g_cursor[d], 1);
    g_csr[pos] = s;
}

// ---------------------------------------------------------------------------
// gather-aggregate (mean): one warp per node, 4-way unrolled
__global__ void __launch_bounds__(256) k_agg(const float* __restrict__ feat_param,
                                             int use_h1) {
    int t = blockIdx.x * blockDim.x + threadIdx.x;
    int node = t >> 5;
    if (node >= NN) return;
    int lane = t & 31;
    const float* feat = use_h1 ? g_h1 : feat_param;

    int start = g_rowptr[node];
    int end = start + g_cnt[node];

    float4 a0 = make_float4(0.f, 0.f, 0.f, 0.f);
    float4 a1 = make_float4(0.f, 0.f, 0.f, 0.f);
    float4 a2 = make_float4(0.f, 0.f, 0.f, 0.f);
    float4 a3 = make_float4(0.f, 0.f, 0.f, 0.f);

    int e = start;
    for (; e + 3 < end; e += 4) {
        int s0 = g_csr[e];
        int s1 = g_csr[e + 1];
        int s2 = g_csr[e + 2];
        int s3 = g_csr[e + 3];
        float4 v0 = *((const float4*)(feat + (size_t)s0 * D) + lane);
        float4 v1 = *((const float4*)(feat + (size_t)s1 * D) + lane);
        float4 v2 = *((const float4*)(feat + (size_t)s2 * D) + lane);
        float4 v3 = *((const float4*)(feat + (size_t)s3 * D) + lane);
        a0.x += v0.x; a0.y += v0.y; a0.z += v0.z; a0.w += v0.w;
        a1.x += v1.x; a1.y += v1.y; a1.z += v1.z; a1.w += v1.w;
        a2.x += v2.x; a2.y += v2.y; a2.z += v2.z; a2.w += v2.w;
        a3.x += v3.x; a3.y += v3.y; a3.z += v3.z; a3.w += v3.w;
    }
    for (; e < end; e++) {
        int s0 = g_csr[e];
        float4 v0 = *((const float4*)(feat + (size_t)s0 * D) + lane);
        a0.x += v0.x; a0.y += v0.y; a0.z += v0.z; a0.w += v0.w;
    }

    float di = g_dinv[node];
    float4 r;
    r.x = (a0.x + a1.x + a2.x + a3.x) * di;
    r.y = (a0.y + a1.y + a2.y + a3.y) * di;
    r.z = (a0.z + a1.z + a2.z + a3.z) * di;
    r.w = (a0.w + a1.w + a2.w + a3.w) * di;
    *((float4*)(g_agg + (size_t)node * D) + lane) = r;
}

// ---------------------------------------------------------------------------
// common MMA helpers
__device__ __forceinline__ uint32_t smem_u32(const void* p) {
    uint32_t a;
    asm("{ .reg .u64 t; cvta.to.shared.u64 t, %1; cvt.u32.u64 %0, t; }"
        : "=r"(a) : "l"(p));
    return a;
}

__device__ __forceinline__ void ldm_x4(uint32_t addr, uint32_t* r) {
    asm volatile("ldmatrix.sync.aligned.m8n8.x4.shared.b16 {%0,%1,%2,%3}, [%4];"
                 : "=r"(r[0]), "=r"(r[1]), "=r"(r[2]), "=r"(r[3]) : "r"(addr));
}

__device__ __forceinline__ void mma_bf16(float* d, const uint32_t* a,
                                         const uint32_t* b) {
    asm volatile(
        "mma.sync.aligned.m16n8k16.row.col.f32.bf16.bf16.f32 "
        "{%0,%1,%2,%3}, {%4,%5,%6,%7}, {%8,%9}, {%0,%1,%2,%3};"
        : "+f"(d[0]), "+f"(d[1]), "+f"(d[2]), "+f"(d[3])
        : "r"(a[0]), "r"(a[1]), "r"(a[2]), "r"(a[3]), "r"(b[0]), "r"(b[1]));
}

__device__ __forceinline__ void cvt_pair(float x0, float x1, uint32_t& hi,
                                         uint32_t& lo) {
    __nv_bfloat16 h0 = __float2bfloat16(x0);
    __nv_bfloat16 h1 = __float2bfloat16(x1);
    float r0 = x0 - __bfloat162float(h0);
    float r1 = x1 - __bfloat162float(h1);
    __nv_bfloat162 hp(h0, h1);
    __nv_bfloat162 lp(__float2bfloat16(r0), __float2bfloat16(r1));
    hi = *reinterpret_cast<uint32_t*>(&hp);
    lo = *reinterpret_cast<uint32_t*>(&lp);
}

// ---------------------------------------------------------------------------
// mma.sync bf16 layer with hi/lo split (3 passes: hh + hl + lh). 512 threads.
#define TILES_PER_BLK 3
#define NTILES ((NN + 127) / 128)                               // 391
#define MMA_GRID ((NTILES + TILES_PER_BLK - 1) / TILES_PER_BLK) // 131

#define SB_OFF   0
#define A_HI_OFF 1024
#define A_LO_OFF (A_HI_OFF + 34816)       // 128 rows * 272B
#define B_HI_OFF (A_LO_OFF + 34816)       // 70656
#define B_LO_OFF (B_HI_OFF + 67584)       // 128 rows * 528B
#define SMEM_MMA_BYTES (B_LO_OFF + 67584) // 205824
#define RSA 272
#define RSB 528

__global__ void __launch_bounds__(512, 1) k_layer_mma(const float* __restrict__ xin_param,
                                                      const float* __restrict__ Wl,
                                                      const float* __restrict__ Wr,
                                                      const float* __restrict__ b,
                                                      int first) {
    extern __shared__ char smem[];
    uint32_t sbase = smem_u32(smem);
    float* sbias = (float*)(smem + SB_OFF);

    const float* xin = first ? xin_param : g_h1;
    float* hout = first ? g_h1 : g_h2;

    int tid = threadIdx.x;
    int lane = tid & 31;
    int wid = tid >> 5;
    int wm = wid >> 2;       // 0..3 -> m offset wm*32
    int wn = wid & 3;        // 0..3 -> n offset wn*32

    if (tid < 128) sbias[tid] = b[tid];

    // convert weights once: [o][k] hi/lo bf16, float4 loads
    for (int i = 0; i < 16; i++) {
        int p = tid + i * 512;          // 0..8191
        int o = p >> 6;
        int kq = p & 63;                // quad index, k = kq*4
        float4 v = (kq < 32) ? *(const float4*)(Wl + o * 128 + kq * 4)
                             : *(const float4*)(Wr + o * 128 + (kq - 32) * 4);
        uint32_t h0, l0, h1, l1;
        cvt_pair(v.x, v.y, h0, l0);
        cvt_pair(v.z, v.w, h1, l1);
        *(uint2*)(smem + B_HI_OFF + o * RSB + kq * 8) = make_uint2(h0, h1);
        *(uint2*)(smem + B_LO_OFF + o * RSB + kq * 8) = make_uint2(l0, l1);
    }
    __syncthreads();

    int sub = lane >> 3;
    int rin = lane & 7;
    int a_row = (sub & 1) * 8 + rin;
    int a_kof = (sub >> 1) * 8;
    int b_row = (sub >> 1) * 8 + rin;
    int b_kof = (sub & 1) * 8;

    for (int t = 0; t < TILES_PER_BLK; t++) {
        int node0 = (blockIdx.x * TILES_PER_BLK + t) * 128;
        if (node0 >= NN) break;

        float acc[2][4][4];
#pragma unroll
        for (int mt = 0; mt < 2; mt++)
#pragma unroll
            for (int nt = 0; nt < 4; nt++)
#pragma unroll
                for (int j = 0; j < 4; j++) acc[mt][nt][j] = 0.f;

        for (int half = 0; half < 2; half++) {
            const float* Asrc = half ? xin : g_agg;
            // convert A half: 128 rows x 32 quads, float4 loads
            for (int i = 0; i < 8; i++) {
                int p = tid + i * 512;       // 0..4095
                int r = p >> 5;
                int kq = p & 31;             // k = kq*4
                int node = node0 + r;
                float4 v = make_float4(0.f, 0.f, 0.f, 0.f);
                if (node < NN) v = *(const float4*)(Asrc + (size_t)node * D + kq * 4);
                uint32_t h0, l0, h1, l1;
                cvt_pair(v.x, v.y, h0, l0);
                cvt_pair(v.z, v.w, h1, l1);
                *(uint2*)(smem + A_HI_OFF + r * RSA + kq * 8) = make_uint2(h0, h1);
                *(uint2*)(smem + A_LO_OFF + r * RSA + kq * 8) = make_uint2(l0, l1);
            }
            __syncthreads();

#pragma unroll
            for (int ks = 0; ks < 8; ks++) {
                int akc = ks * 16 + a_kof;
                int bkc = half * 128 + ks * 16 + b_kof;

                uint32_t ah[2][4], al[2][4];
#pragma unroll
                for (int mt = 0; mt < 2; mt++) {
                    uint32_t ro = (uint32_t)((wm * 32 + mt * 16 + a_row) * RSA + akc * 2);
                    ldm_x4(sbase + A_HI_OFF + ro, ah[mt]);
                    ldm_x4(sbase + A_LO_OFF + ro, al[mt]);
                }
                uint32_t bh[2][4], bl[2][4];
#pragma unroll
                for (int np = 0; np < 2; np++) {
                    uint32_t ro = (uint32_t)((wn * 32 + np * 16 + b_row) * RSB + bkc * 2);
                    ldm_x4(sbase + B_HI_OFF + ro, bh[np]);
                    ldm_x4(sbase + B_LO_OFF + ro, bl[np]);
                }
#pragma unroll
                for (int mt = 0; mt < 2; mt++) {
#pragma unroll
                    for (int nt = 0; nt < 4; nt++) {
                        const uint32_t* Bh = &bh[nt >> 1][(nt & 1) * 2];
                        const uint32_t* Bl = &bl[nt >> 1][(nt & 1) * 2];
                        mma_bf16(acc[mt][nt], ah[mt], Bh);
                        mma_bf16(acc[mt][nt], ah[mt], Bl);
                        mma_bf16(acc[mt][nt], al[mt], Bh);
                    }
                }
            }
            __syncthreads();
        }

        int qr = lane >> 2;
        int qc = (lane & 3) * 2;
#pragma unroll
        for (int mt = 0; mt < 2; mt++) {
            int n0 = node0 + wm * 32 + mt * 16 + qr;
            int n1 = n0 + 8;
#pragma unroll
            for (int nt = 0; nt < 4; nt++) {
                int o = wn * 32 + nt * 8 + qc;
                float b0 = sbias[o], b1 = sbias[o + 1];
                if (n0 < NN) {
                    float2 v;
                    v.x = fmaxf(acc[mt][nt][0] + b0, 0.f);
                    v.y = fmaxf(acc[mt][nt][1] + b1, 0.f);
                    *(float2*)(hout + (size_t)n0 * D + o) = v;
                }
                if (n1 < NN) {
                    float2 v;
                    v.x = fmaxf(acc[mt][nt][2] + b0, 0.f);
                    v.y = fmaxf(acc[mt][nt][3] + b1, 0.f);
                    *(float2*)(hout + (size_t)n1 * D + o) = v;
                }
            }
        }
        __syncthreads();
    }
}

// ---------------------------------------------------------------------------
// final head on MMA: logits = [h1|h2] @ W_lin^T + b_lin ; log_softmax in regs.
#define RSF 528
#define FA_HI 1024
#define FA_LO (FA_HI + 128 * RSF)            // 68608
#define FB_HI (FA_LO + 128 * RSF)            // 136192
#define FB_LO (FB_HI + 48 * RSF)             // 161536
#define SMEM_FIN_BYTES (FB_LO + 48 * RSF)    // 186880

__global__ void __launch_bounds__(256, 1) k_final_mma(const float* __restrict__ Wlin,
                                                      const float* __restrict__ blin,
                                                      float* __restrict__ out) {
    extern __shared__ char smem[];
    uint32_t sbase = smem_u32(smem);
    float* sbias = (float*)(smem + SB_OFF);

    int tid = threadIdx.x;
    int lane = tid & 31;
    int wid = tid >> 5;
    int node0 = blockIdx.x * 128;

    if (tid < 48) sbias[tid] = (tid < DOUT) ? blin[tid] : 0.f;

    // Wlin [40][256] -> padded 48 rows hi/lo (float4 loads)
    for (int i = 0; i < 12; i++) {
        int p = tid + i * 256;          // 0..3071
        int o = p >> 6;
        int kq = p & 63;
        float4 v = make_float4(0.f, 0.f, 0.f, 0.f);
        if (o < DOUT) v = *(const float4*)(Wlin + o * 256 + kq * 4);
        uint32_t h0, l0, h1, l1;
        cvt_pair(v.x, v.y, h0, l0);
        cvt_pair(v.z, v.w, h1, l1);
        *(uint2*)(smem + FB_HI + o * RSF + kq * 8) = make_uint2(h0, h1);
        *(uint2*)(smem + FB_LO + o * RSF + kq * 8) = make_uint2(l0, l1);
    }

    // A = [h1 | h2] tile: 128 rows x 64 quads (float4 loads)
    for (int i = 0; i < 32; i++) {
        int p = tid + i * 256;          // 0..8191
        int r = p >> 6;
        int kq = p & 63;
        int node = node0 + r;
        float4 v = make_float4(0.f, 0.f, 0.f, 0.f);
        if (node < NN) {
            const float* src = (kq < 32) ? (g_h1 + (size_t)node * D + kq * 4)
                                         : (g_h2 + (size_t)node * D + (kq - 32) * 4);
            v = *(const float4*)src;
        }
        uint32_t h0, l0, h1, l1;
        cvt_pair(v.x, v.y, h0, l0);
        cvt_pair(v.z, v.w, h1, l1);
        *(uint2*)(smem + FA_HI + r * RSF + kq * 8) = make_uint2(h0, h1);
        *(uint2*)(smem + FA_LO + r * RSF + kq * 8) = make_uint2(l0, l1);
    }
    __syncthreads();

    int sub = lane >> 3;
    int rin = lane & 7;
    int a_row = (sub & 1) * 8 + rin;
    int a_kof = (sub >> 1) * 8;
    int b_row = (sub >> 1) * 8 + rin;
    int b_kof = (sub & 1) * 8;

    float acc[5][4];
#pragma unroll
    for (int nt = 0; nt < 5; nt++)
#pragma unroll
        for (int j = 0; j < 4; j++) acc[nt][j] = 0.f;

#pragma unroll
    for (int ks = 0; ks < 16; ks++) {
        uint32_t ah[4], al[4];
        {
            uint32_t ro = (uint32_t)((wid * 16 + a_row) * RSF + (ks * 16 + a_kof) * 2);
            ldm_x4(sbase + FA_HI + ro, ah);
            ldm_x4(sbase + FA_LO + ro, al);
        }
        uint32_t bh[3][4], bl[3][4];
#pragma unroll
        for (int np = 0; np < 3; np++) {
            uint32_t ro = (uint32_t)((np * 16 + b_row) * RSF + (ks * 16 + b_kof) * 2);
            ldm_x4(sbase + FB_HI + ro, bh[np]);
            ldm_x4(sbase + FB_LO + ro, bl[np]);
        }
#pragma unroll
        for (int nt = 0; nt < 5; nt++) {
            const uint32_t* Bh = &bh[nt >> 1][(nt & 1) * 2];
            const uint32_t* Bl = &bl[nt >> 1][(nt & 1) * 2];
            mma_bf16(acc[nt], ah, Bh);
            mma_bf16(acc[nt], ah, Bl);
            mma_bf16(acc[nt], al, Bh);
        }
    }

    int qc = (lane & 3) * 2;
#pragma unroll
    for (int nt = 0; nt < 5; nt++) {
        int o = nt * 8 + qc;
        acc[nt][0] += sbias[o];
        acc[nt][1] += sbias[o + 1];
        acc[nt][2] += sbias[o];
        acc[nt][3] += sbias[o + 1];
    }

    float m0 = -1e30f, m1 = -1e30f;
#pragma unroll
    for (int nt = 0; nt < 5; nt++) {
        m0 = fmaxf(m0, fmaxf(acc[nt][0], acc[nt][1]));
        m1 = fmaxf(m1, fmaxf(acc[nt][2], acc[nt][3]));
    }
#pragma unroll
    for (int d = 1; d <= 2; d <<= 1) {
        m0 = fmaxf(m0, __shfl_xor_sync(0xffffffffu, m0, d));
        m1 = fmaxf(m1, __shfl_xor_sync(0xffffffffu, m1, d));
    }
    float s0 = 0.f, s1 = 0.f;
#pragma unroll
    for (int nt = 0; nt < 5; nt++) {
        s0 += expf(acc[nt][0] - m0) + expf(acc[nt][1] - m0);
        s1 += expf(acc[nt][2] - m1) + expf(acc[nt][3] - m1);
    }
#pragma unroll
    for (int d = 1; d <= 2; d <<= 1) {
        s0 += __shfl_xor_sync(0xffffffffu, s0, d);
        s1 += __shfl_xor_sync(0xffffffffu, s1, d);
    }
    float lse0 = m0 + logf(s0);
    float lse1 = m1 + logf(s1);

    int qr = lane >> 2;
    int r0 = node0 + wid * 16 + qr;
    int r1 = r0 + 8;
#pragma unroll
    for (int nt = 0; nt < 5; nt++) {
        int o = nt * 8 + qc;
        if (r0 < NN) {
            float2 v = make_float2(acc[nt][0] - lse0, acc[nt][1] - lse0);
            *(float2*)(out + (size_t)r0 * DOUT + o) = v;
        }
        if (r1 < NN) {
            float2 v = make_float2(acc[nt][2] - lse1, acc[nt][3] - lse1);
            *(float2*)(out + (size_t)r1 * DOUT + o) = v;
        }
    }
}

// ---------------------------------------------------------------------------
extern "C" void kernel_launch(void* const* d_in, const int* in_sizes, int n_in,
                              void* d_out, int out_size) {
    const float* x    = (const float*)d_in[0];
    const void*  ei   = d_in[1];
    const float* W1l  = (const float*)d_in[2];
    const float* b1   = (const float*)d_in[3];
    const float* W1r  = (const float*)d_in[4];
    const float* W2l  = (const float*)d_in[5];
    const float* b2   = (const float*)d_in[6];
    const float* W2r  = (const float*)d_in[7];
    const float* Wlin = (const float*)d_in[8];
    const float* blin = (const float*)d_in[9];
    float*       out  = (float*)d_out;

    cudaFuncSetAttribute(k_layer_mma, cudaFuncAttributeMaxDynamicSharedMemorySize,
                         SMEM_MMA_BYTES);
    cudaFuncSetAttribute(k_final_mma, cudaFuncAttributeMaxDynamicSharedMemorySize,
                         SMEM_FIN_BYTES);

    const int edge_blocks = (NE + 255) / 256;      // 3125
    const int agg_blocks  = (NN * 32 + 255) / 256; // 6250

    // CSR build: init, hist, order-free alloc, fill  (4 launches)
    k_init<<<NBLK, 256>>>((const int*)ei);
    k_hist<<<edge_blocks, 256>>>(ei);
    k_alloc<<<NBLK, 256>>>();
    k_fill<<<edge_blocks, 256>>>(ei);

    // layer 1
    k_agg<<<agg_blocks, 256>>>(x, 0);
    k_layer_mma<<<MMA_GRID, 512, SMEM_MMA_BYTES>>>(x, W1l, W1r, b1, 1);

    // layer 2
    k_agg<<<agg_blocks, 256>>>(nullptr, 1);
    k_layer_mma<<<MMA_GRID, 512, SMEM_MMA_BYTES>>>(nullptr, W2l, W2r, b2, 0);

    // head
    k_final_mma<<<NTILES, 256, SMEM_FIN_BYTES>>>(Wlin, blin, out);
}

// round 9
// speedup vs baseline: 1.3297x; 1.0297x over previous
#include <cuda_runtime.h>
#include <cuda_bf16.h>
#include <math.h>
#include <stdint.h>

#define NN   50000
#define NE   800000
#define D    128
#define DOUT 40
#define NBLK ((NN + 255) / 256)   // 196

// scratch (allocation-free rule: __device__ globals)
__device__ float g_agg[NN * D];
__device__ float g_h1[NN * D];
__device__ float g_h2[NN * D];
__device__ float g_dinv[NN];
__device__ int   g_cnt[NN];
__device__ int   g_rowptr[NN];
__device__ int   g_cursor[NN];
__device__ int   g_csr[NE];
__device__ int   g_is64;
__device__ int   g_total;

// ---------------------------------------------------------------------------
__global__ void k_init(const int* __restrict__ ei32) {
    int i = blockIdx.x * 256 + threadIdx.x;
    if (i < NN) g_cnt[i] = 0;
    if (blockIdx.x == 0) {
        int nz = (ei32[2 * threadIdx.x + 1] != 0) ? 1 : 0;
        int cnt_nz = __syncthreads_count(nz);
        if (threadIdx.x == 0) {
            g_is64 = (cnt_nz == 0) ? 1 : 0;
            g_total = 0;
        }
    }
}

// 2 edges per thread, vector loads of the dst stream
__global__ void __launch_bounds__(256) k_hist(const void* __restrict__ ei) {
    int e0 = (blockIdx.x * blockDim.x + threadIdx.x) * 2;
    if (e0 >= NE) return;
    int d0, d1;
    if (g_is64) {
        longlong2 v = *(const longlong2*)((const long long*)ei + NE + e0);
        d0 = (int)v.x; d1 = (int)v.y;
    } else {
        int2 v = *(const int2*)((const int*)ei + NE + e0);
        d0 = v.x; d1 = v.y;
    }
    atomicAdd(&g_cnt[d0], 1);
    atomicAdd(&g_cnt[d1], 1);
}

// order-free CSR slot allocation
__global__ void __launch_bounds__(256) k_alloc() {
    int i = blockIdx.x * 256 + threadIdx.x;
    if (i < NN) {
        int c = g_cnt[i];
        int rp = atomicAdd(&g_total, c);
        g_rowptr[i] = rp;
        g_cursor[i] = rp;
        g_dinv[i] = 1.0f / (float)max(c, 1);
    }
}

// 2 edges per thread, vector loads of src+dst streams
__global__ void __launch_bounds__(256) k_fill(const void* __restrict__ ei) {
    int e0 = (blockIdx.x * blockDim.x + threadIdx.x) * 2;
    if (e0 >= NE) return;
    int s0, s1, d0, d1;
    if (g_is64) {
        longlong2 vs = *(const longlong2*)((const long long*)ei + e0);
        longlong2 vd = *(const longlong2*)((const long long*)ei + NE + e0);
        s0 = (int)vs.x; s1 = (int)vs.y; d0 = (int)vd.x; d1 = (int)vd.y;
    } else {
        int2 vs = *(const int2*)((const int*)ei + e0);
        int2 vd = *(const int2*)((const int*)ei + NE + e0);
        s0 = vs.x; s1 = vs.y; d0 = vd.x; d1 = vd.y;
    }
    g_csr[atomicAdd(&g_cursor[d0], 1)] = s0;
    g_csr[atomicAdd(&g_cursor[d1], 1)] = s1;
}

// ---------------------------------------------------------------------------
// gather-aggregate (mean): one warp per node, 4-way unrolled
__global__ void __launch_bounds__(256) k_agg(const float* __restrict__ feat_param,
                                             int use_h1) {
    int t = blockIdx.x * blockDim.x + threadIdx.x;
    int node = t >> 5;
    if (node >= NN) return;
    int lane = t & 31;
    const float* feat = use_h1 ? g_h1 : feat_param;

    int start = g_rowptr[node];
    int end = start + g_cnt[node];

    float4 a0 = make_float4(0.f, 0.f, 0.f, 0.f);
    float4 a1 = make_float4(0.f, 0.f, 0.f, 0.f);
    float4 a2 = make_float4(0.f, 0.f, 0.f, 0.f);
    float4 a3 = make_float4(0.f, 0.f, 0.f, 0.f);

    int e = start;
    for (; e + 3 < end; e += 4) {
        int s0 = g_csr[e];
        int s1 = g_csr[e + 1];
        int s2 = g_csr[e + 2];
        int s3 = g_csr[e + 3];
        float4 v0 = *((const float4*)(feat + (size_t)s0 * D) + lane);
        float4 v1 = *((const float4*)(feat + (size_t)s1 * D) + lane);
        float4 v2 = *((const float4*)(feat + (size_t)s2 * D) + lane);
        float4 v3 = *((const float4*)(feat + (size_t)s3 * D) + lane);
        a0.x += v0.x; a0.y += v0.y; a0.z += v0.z; a0.w += v0.w;
        a1.x += v1.x; a1.y += v1.y; a1.z += v1.z; a1.w += v1.w;
        a2.x += v2.x; a2.y += v2.y; a2.z += v2.z; a2.w += v2.w;
        a3.x += v3.x; a3.y += v3.y; a3.z += v3.z; a3.w += v3.w;
    }
    for (; e < end; e++) {
        int s0 = g_csr[e];
        float4 v0 = *((const float4*)(feat + (size_t)s0 * D) + lane);
        a0.x += v0.x; a0.y += v0.y; a0.z += v0.z; a0.w += v0.w;
    }

    float di = g_dinv[node];
    float4 r;
    r.x = (a0.x + a1.x + a2.x + a3.x) * di;
    r.y = (a0.y + a1.y + a2.y + a3.y) * di;
    r.z = (a0.z + a1.z + a2.z + a3.z) * di;
    r.w = (a0.w + a1.w + a2.w + a3.w) * di;
    *((float4*)(g_agg + (size_t)node * D) + lane) = r;
}

// ---------------------------------------------------------------------------
// common MMA helpers
__device__ __forceinline__ uint32_t smem_u32(const void* p) {
    uint32_t a;
    asm("{ .reg .u64 t; cvta.to.shared.u64 t, %1; cvt.u32.u64 %0, t; }"
        : "=r"(a) : "l"(p));
    return a;
}

__device__ __forceinline__ void ldm_x4(uint32_t addr, uint32_t* r) {
    asm volatile("ldmatrix.sync.aligned.m8n8.x4.shared.b16 {%0,%1,%2,%3}, [%4];"
                 : "=r"(r[0]), "=r"(r[1]), "=r"(r[2]), "=r"(r[3]) : "r"(addr));
}

__device__ __forceinline__ void mma_bf16(float* d, const uint32_t* a,
                                         const uint32_t* b) {
    asm volatile(
        "mma.sync.aligned.m16n8k16.row.col.f32.bf16.bf16.f32 "
        "{%0,%1,%2,%3}, {%4,%5,%6,%7}, {%8,%9}, {%0,%1,%2,%3};"
        : "+f"(d[0]), "+f"(d[1]), "+f"(d[2]), "+f"(d[3])
        : "r"(a[0]), "r"(a[1]), "r"(a[2]), "r"(a[3]), "r"(b[0]), "r"(b[1]));
}

__device__ __forceinline__ void cvt_pair(float x0, float x1, uint32_t& hi,
                                         uint32_t& lo) {
    __nv_bfloat16 h0 = __float2bfloat16(x0);
    __nv_bfloat16 h1 = __float2bfloat16(x1);
    float r0 = x0 - __bfloat162float(h0);
    float r1 = x1 - __bfloat162float(h1);
    __nv_bfloat162 hp(h0, h1);
    __nv_bfloat162 lp(__float2bfloat16(r0), __float2bfloat16(r1));
    hi = *reinterpret_cast<uint32_t*>(&hp);
    lo = *reinterpret_cast<uint32_t*>(&lp);
}

// ---------------------------------------------------------------------------
// mma.sync bf16 layer, hi/lo split, register-prefetch double buffering.
#define TILES_PER_BLK 3
#define NTILES ((NN + 127) / 128)                               // 391
#define MMA_GRID ((NTILES + TILES_PER_BLK - 1) / TILES_PER_BLK) // 131

#define SB_OFF   0
#define A_HI_OFF 1024
#define A_LO_OFF (A_HI_OFF + 34816)       // 128 rows * 272B
#define B_HI_OFF (A_LO_OFF + 34816)       // 70656
#define B_LO_OFF (B_HI_OFF + 67584)       // 128 rows * 528B
#define SMEM_MMA_BYTES (B_LO_OFF + 67584) // 205824
#define RSA 272
#define RSB 528

// prefetch one A-half (8 float4 per thread) into registers
#define PREF_A(Asrc, node0_)                                            \
    do {                                                                \
        _Pragma("unroll")                                               \
        for (int i = 0; i < 8; i++) {                                   \
            int p = tid + i * 512;                                      \
            int r = p >> 5;                                             \
            int kq = p & 31;                                            \
            int node = (node0_) + r;                                    \
            pf[i] = (node < NN)                                         \
                ? *(const float4*)((Asrc) + (size_t)node * D + kq * 4)  \
                : make_float4(0.f, 0.f, 0.f, 0.f);                      \
        }                                                               \
    } while (0)

__global__ void __launch_bounds__(512, 1) k_layer_mma(const float* __restrict__ xin_param,
                                                      const float* __restrict__ Wl,
                                                      const float* __restrict__ Wr,
                                                      const float* __restrict__ b,
                                                      int first) {
    extern __shared__ char smem[];
    uint32_t sbase = smem_u32(smem);
    float* sbias = (float*)(smem + SB_OFF);

    const float* xin = first ? xin_param : g_h1;
    float* hout = first ? g_h1 : g_h2;

    int tid = threadIdx.x;
    int lane = tid & 31;
    int wid = tid >> 5;
    int wm = wid >> 2;
    int wn = wid & 3;

    if (tid < 128) sbias[tid] = b[tid];

    float4 pf[8];
    // prefetch first tile's agg half while we convert weights
    PREF_A(g_agg, blockIdx.x * TILES_PER_BLK * 128);

    // convert weights once: [o][k] hi/lo bf16, float4 loads
    for (int i = 0; i < 16; i++) {
        int p = tid + i * 512;
        int o = p >> 6;
        int kq = p & 63;
        float4 v = (kq < 32) ? *(const float4*)(Wl + o * 128 + kq * 4)
                             : *(const float4*)(Wr + o * 128 + (kq - 32) * 4);
        uint32_t h0, l0, h1, l1;
        cvt_pair(v.x, v.y, h0, l0);
        cvt_pair(v.z, v.w, h1, l1);
        *(uint2*)(smem + B_HI_OFF + o * RSB + kq * 8) = make_uint2(h0, h1);
        *(uint2*)(smem + B_LO_OFF + o * RSB + kq * 8) = make_uint2(l0, l1);
    }
    __syncthreads();

    int sub = lane >> 3;
    int rin = lane & 7;
    int a_row = (sub & 1) * 8 + rin;
    int a_kof = (sub >> 1) * 8;
    int b_row = (sub >> 1) * 8 + rin;
    int b_kof = (sub & 1) * 8;

    for (int t = 0; t < TILES_PER_BLK; t++) {
        int node0 = (blockIdx.x * TILES_PER_BLK + t) * 128;
        if (node0 >= NN) break;

        float acc[2][4][4];
#pragma unroll
        for (int mt = 0; mt < 2; mt++)
#pragma unroll
            for (int nt = 0; nt < 4; nt++)
#pragma unroll
                for (int j = 0; j < 4; j++) acc[mt][nt][j] = 0.f;

        for (int half = 0; half < 2; half++) {
            // store prefetched A half (cvt + STS only)
#pragma unroll
            for (int i = 0; i < 8; i++) {
                int p = tid + i * 512;
                int r = p >> 5;
                int kq = p & 31;
                uint32_t h0, l0, h1, l1;
                cvt_pair(pf[i].x, pf[i].y, h0, l0);
                cvt_pair(pf[i].z, pf[i].w, h1, l1);
                *(uint2*)(smem + A_HI_OFF + r * RSA + kq * 8) = make_uint2(h0, h1);
                *(uint2*)(smem + A_LO_OFF + r * RSA + kq * 8) = make_uint2(l0, l1);
            }
            __syncthreads();

            // issue next prefetch (hidden under the MMA loop below)
            if (half == 0) {
                PREF_A(xin, node0);
            } else if (t + 1 < TILES_PER_BLK) {
                PREF_A(g_agg, node0 + 128);
            }

#pragma unroll
            for (int ks = 0; ks < 8; ks++) {
                int akc = ks * 16 + a_kof;
                int bkc = half * 128 + ks * 16 + b_kof;

                uint32_t ah[2][4], al[2][4];
#pragma unroll
                for (int mt = 0; mt < 2; mt++) {
                    uint32_t ro = (uint32_t)((wm * 32 + mt * 16 + a_row) * RSA + akc * 2);
                    ldm_x4(sbase + A_HI_OFF + ro, ah[mt]);
                    ldm_x4(sbase + A_LO_OFF + ro, al[mt]);
                }
                uint32_t bh[2][4], bl[2][4];
#pragma unroll
                for (int np = 0; np < 2; np++) {
                    uint32_t ro = (uint32_t)((wn * 32 + np * 16 + b_row) * RSB + bkc * 2);
                    ldm_x4(sbase + B_HI_OFF + ro, bh[np]);
                    ldm_x4(sbase + B_LO_OFF + ro, bl[np]);
                }
#pragma unroll
                for (int mt = 0; mt < 2; mt++) {
#pragma unroll
                    for (int nt = 0; nt < 4; nt++) {
                        const uint32_t* Bh = &bh[nt >> 1][(nt & 1) * 2];
                        const uint32_t* Bl = &bl[nt >> 1][(nt & 1) * 2];
                        mma_bf16(acc[mt][nt], ah[mt], Bh);
                        mma_bf16(acc[mt][nt], ah[mt], Bl);
                        mma_bf16(acc[mt][nt], al[mt], Bh);
                    }
                }
            }
            __syncthreads();
        }

        int qr = lane >> 2;
        int qc = (lane & 3) * 2;
#pragma unroll
        for (int mt = 0; mt < 2; mt++) {
            int n0 = node0 + wm * 32 + mt * 16 + qr;
            int n1 = n0 + 8;
#pragma unroll
            for (int nt = 0; nt < 4; nt++) {
                int o = wn * 32 + nt * 8 + qc;
                float b0 = sbias[o], b1 = sbias[o + 1];
                if (n0 < NN) {
                    float2 v;
                    v.x = fmaxf(acc[mt][nt][0] + b0, 0.f);
                    v.y = fmaxf(acc[mt][nt][1] + b1, 0.f);
                    *(float2*)(hout + (size_t)n0 * D + o) = v;
                }
                if (n1 < NN) {
                    float2 v;
                    v.x = fmaxf(acc[mt][nt][2] + b0, 0.f);
                    v.y = fmaxf(acc[mt][nt][3] + b1, 0.f);
                    *(float2*)(hout + (size_t)n1 * D + o) = v;
                }
            }
        }
        __syncthreads();
    }
}

// ---------------------------------------------------------------------------
// final head on MMA: logits = [h1|h2] @ W_lin^T + b_lin ; log_softmax in regs.
#define RSF 528
#define FA_HI 1024
#define FA_LO (FA_HI + 128 * RSF)
#define FB_HI (FA_LO + 128 * RSF)
#define FB_LO (FB_HI + 48 * RSF)
#define SMEM_FIN_BYTES (FB_LO + 48 * RSF)

__global__ void __launch_bounds__(256, 1) k_final_mma(const float* __restrict__ Wlin,
                                                      const float* __restrict__ blin,
                                                      float* __restrict__ out) {
    extern __shared__ char smem[];
    uint32_t sbase = smem_u32(smem);
    float* sbias = (float*)(smem + SB_OFF);

    int tid = threadIdx.x;
    int lane = tid & 31;
    int wid = tid >> 5;
    int node0 = blockIdx.x * 128;

    if (tid < 48) sbias[tid] = (tid < DOUT) ? blin[tid] : 0.f;

    for (int i = 0; i < 12; i++) {
        int p = tid + i * 256;
        int o = p >> 6;
        int kq = p & 63;
        float4 v = make_float4(0.f, 0.f, 0.f, 0.f);
        if (o < DOUT) v = *(const float4*)(Wlin + o * 256 + kq * 4);
        uint32_t h0, l0, h1, l1;
        cvt_pair(v.x, v.y, h0, l0);
        cvt_pair(v.z, v.w, h1, l1);
        *(uint2*)(smem + FB_HI + o * RSF + kq * 8) = make_uint2(h0, h1);
        *(uint2*)(smem + FB_LO + o * RSF + kq * 8) = make_uint2(l0, l1);
    }

    for (int i = 0; i < 32; i++) {
        int p = tid + i * 256;
        int r = p >> 6;
        int kq = p & 63;
        int node = node0 + r;
        float4 v = make_float4(0.f, 0.f, 0.f, 0.f);
        if (node < NN) {
            const float* src = (kq < 32) ? (g_h1 + (size_t)node * D + kq * 4)
                                         : (g_h2 + (size_t)node * D + (kq - 32) * 4);
            v = *(const float4*)src;
        }
        uint32_t h0, l0, h1, l1;
        cvt_pair(v.x, v.y, h0, l0);
        cvt_pair(v.z, v.w, h1, l1);
        *(uint2*)(smem + FA_HI + r * RSF + kq * 8) = make_uint2(h0, h1);
        *(uint2*)(smem + FA_LO + r * RSF + kq * 8) = make_uint2(l0, l1);
    }
    __syncthreads();

    int sub = lane >> 3;
    int rin = lane & 7;
    int a_row = (sub & 1) * 8 + rin;
    int a_kof = (sub >> 1) * 8;
    int b_row = (sub >> 1) * 8 + rin;
    int b_kof = (sub & 1) * 8;

    float acc[5][4];
#pragma unroll
    for (int nt = 0; nt < 5; nt++)
#pragma unroll
        for (int j = 0; j < 4; j++) acc[nt][j] = 0.f;

#pragma unroll
    for (int ks = 0; ks < 16; ks++) {
        uint32_t ah[4], al[4];
        {
            uint32_t ro = (uint32_t)((wid * 16 + a_row) * RSF + (ks * 16 + a_kof) * 2);
            ldm_x4(sbase + FA_HI + ro, ah);
            ldm_x4(sbase + FA_LO + ro, al);
        }
        uint32_t bh[3][4], bl[3][4];
#pragma unroll
        for (int np = 0; np < 3; np++) {
            uint32_t ro = (uint32_t)((np * 16 + b_row) * RSF + (ks * 16 + b_kof) * 2);
            ldm_x4(sbase + FB_HI + ro, bh[np]);
            ldm_x4(sbase + FB_LO + ro, bl[np]);
        }
#pragma unroll
        for (int nt = 0; nt < 5; nt++) {
            const uint32_t* Bh = &bh[nt >> 1][(nt & 1) * 2];
            const uint32_t* Bl = &bl[nt >> 1][(nt & 1) * 2];
            mma_bf16(acc[nt], ah, Bh);
            mma_bf16(acc[nt], ah, Bl);
            mma_bf16(acc[nt], al, Bh);
        }
    }

    int qc = (lane & 3) * 2;
#pragma unroll
    for (int nt = 0; nt < 5; nt++) {
        int o = nt * 8 + qc;
        acc[nt][0] += sbias[o];
        acc[nt][1] += sbias[o + 1];
        acc[nt][2] += sbias[o];
        acc[nt][3] += sbias[o + 1];
    }

    float m0 = -1e30f, m1 = -1e30f;
#pragma unroll
    for (int nt = 0; nt < 5; nt++) {
        m0 = fmaxf(m0, fmaxf(acc[nt][0], acc[nt][1]));
        m1 = fmaxf(m1, fmaxf(acc[nt][2], acc[nt][3]));
    }
#pragma unroll
    for (int d = 1; d <= 2; d <<= 1) {
        m0 = fmaxf(m0, __shfl_xor_sync(0xffffffffu, m0, d));
        m1 = fmaxf(m1, __shfl_xor_sync(0xffffffffu, m1, d));
    }
    float s0 = 0.f, s1 = 0.f;
#pragma unroll
    for (int nt = 0; nt < 5; nt++) {
        s0 += expf(acc[nt][0] - m0) + expf(acc[nt][1] - m0);
        s1 += expf(acc[nt][2] - m1) + expf(acc[nt][3] - m1);
    }
#pragma unroll
    for (int d = 1; d <= 2; d <<= 1) {
        s0 += __shfl_xor_sync(0xffffffffu, s0, d);
        s1 += __shfl_xor_sync(0xffffffffu, s1, d);
    }
    float lse0 = m0 + logf(s0);
    float lse1 = m1 + logf(s1);

    int qr = lane >> 2;
    int r0 = node0 + wid * 16 + qr;
    int r1 = r0 + 8;
#pragma unroll
    for (int nt = 0; nt < 5; nt++) {
        int o = nt * 8 + qc;
        if (r0 < NN) {
            float2 v = make_float2(acc[nt][0] - lse0, acc[nt][1] - lse0);
            *(float2*)(out + (size_t)r0 * DOUT + o) = v;
        }
        if (r1 < NN) {
            float2 v = make_float2(acc[nt][2] - lse1, acc[nt][3] - lse1);
            *(float2*)(out + (size_t)r1 * DOUT + o) = v;
        }
    }
}

// ---------------------------------------------------------------------------
extern "C" void kernel_launch(void* const* d_in, const int* in_sizes, int n_in,
                              void* d_out, int out_size) {
    const float* x    = (const float*)d_in[0];
    const void*  ei   = d_in[1];
    const float* W1l  = (const float*)d_in[2];
    const float* b1   = (const float*)d_in[3];
    const float* W1r  = (const float*)d_in[4];
    const float* W2l  = (const float*)d_in[5];
    const float* b2   = (const float*)d_in[6];
    const float* W2r  = (const float*)d_in[7];
    const float* Wlin = (const float*)d_in[8];
    const float* blin = (const float*)d_in[9];
    float*       out  = (float*)d_out;

    cudaFuncSetAttribute(k_layer_mma, cudaFuncAttributeMaxDynamicSharedMemorySize,
                         SMEM_MMA_BYTES);
    cudaFuncSetAttribute(k_final_mma, cudaFuncAttributeMaxDynamicSharedMemorySize,
                         SMEM_FIN_BYTES);

    const int pair_blocks = (NE / 2 + 255) / 256;  // 1563
    const int agg_blocks  = (NN * 32 + 255) / 256; // 6250

    // CSR build
    k_init<<<NBLK, 256>>>((const int*)ei);
    k_hist<<<pair_blocks, 256>>>(ei);
    k_alloc<<<NBLK, 256>>>();
    k_fill<<<pair_blocks, 256>>>(ei);

    // layer 1
    k_agg<<<agg_blocks, 256>>>(x, 0);
    k_layer_mma<<<MMA_GRID, 512, SMEM_MMA_BYTES>>>(x, W1l, W1r, b1, 1);

    // layer 2
    k_agg<<<agg_blocks, 256>>>(nullptr, 1);
    k_layer_mma<<<MMA_GRID, 512, SMEM_MMA_BYTES>>>(nullptr, W2l, W2r, b2, 0);

    // head
    k_final_mma<<<NTILES, 256, SMEM_FIN_BYTES>>>(Wlin, blin, out);
}

// round 10
// speedup vs baseline: 1.3738x; 1.0332x over previous
#include <cuda_runtime.h>
#include <cuda_bf16.h>
#include <math.h>
#include <stdint.h>

#define NN   50000
#define NE   800000
#define D    128
#define DOUT 40
#define NBLK ((NN + 255) / 256)   // 196

// scratch (allocation-free rule: __device__ globals)
__device__ float g_agg[NN * D];
__device__ float g_h1[NN * D];
__device__ float g_h2[NN * D];
__device__ float g_dinv[NN];
__device__ int   g_cnt[NN];
__device__ int   g_rowptr[NN];
__device__ int   g_cursor[NN];
__device__ int   g_csr[NE];
__device__ int   g_is64;
__device__ int   g_total;

// ---------------------------------------------------------------------------
__global__ void k_init(const int* __restrict__ ei32) {
    int i = blockIdx.x * 256 + threadIdx.x;
    if (i < NN) g_cnt[i] = 0;
    if (blockIdx.x == 0) {
        int nz = (ei32[2 * threadIdx.x + 1] != 0) ? 1 : 0;
        int cnt_nz = __syncthreads_count(nz);
        if (threadIdx.x == 0) {
            g_is64 = (cnt_nz == 0) ? 1 : 0;
            g_total = 0;
        }
    }
}

// 4 edges per thread: 4 independent atomic chains
__global__ void __launch_bounds__(256) k_hist(const void* __restrict__ ei) {
    int e0 = (blockIdx.x * blockDim.x + threadIdx.x) * 4;
    if (e0 >= NE) return;
    int d[4];
    if (g_is64) {
        longlong2 v0 = *(const longlong2*)((const long long*)ei + NE + e0);
        longlong2 v1 = *(const longlong2*)((const long long*)ei + NE + e0 + 2);
        d[0] = (int)v0.x; d[1] = (int)v0.y; d[2] = (int)v1.x; d[3] = (int)v1.y;
    } else {
        int4 v = *(const int4*)((const int*)ei + NE + e0);
        d[0] = v.x; d[1] = v.y; d[2] = v.z; d[3] = v.w;
    }
#pragma unroll
    for (int j = 0; j < 4; j++) atomicAdd(&g_cnt[d[j]], 1);
}

// order-free CSR slot allocation
__global__ void __launch_bounds__(256) k_alloc() {
    int i = blockIdx.x * 256 + threadIdx.x;
    if (i < NN) {
        int c = g_cnt[i];
        int rp = atomicAdd(&g_total, c);
        g_rowptr[i] = rp;
        g_cursor[i] = rp;
        g_dinv[i] = 1.0f / (float)max(c, 1);
    }
}

// 4 edges per thread: 4 independent atomic->store chains
__global__ void __launch_bounds__(256) k_fill(const void* __restrict__ ei) {
    int e0 = (blockIdx.x * blockDim.x + threadIdx.x) * 4;
    if (e0 >= NE) return;
    int s[4], d[4];
    if (g_is64) {
        longlong2 a0 = *(const longlong2*)((const long long*)ei + e0);
        longlong2 a1 = *(const longlong2*)((const long long*)ei + e0 + 2);
        longlong2 b0 = *(const longlong2*)((const long long*)ei + NE + e0);
        longlong2 b1 = *(const longlong2*)((const long long*)ei + NE + e0 + 2);
        s[0] = (int)a0.x; s[1] = (int)a0.y; s[2] = (int)a1.x; s[3] = (int)a1.y;
        d[0] = (int)b0.x; d[1] = (int)b0.y; d[2] = (int)b1.x; d[3] = (int)b1.y;
    } else {
        int4 vs = *(const int4*)((const int*)ei + e0);
        int4 vd = *(const int4*)((const int*)ei + NE + e0);
        s[0] = vs.x; s[1] = vs.y; s[2] = vs.z; s[3] = vs.w;
        d[0] = vd.x; d[1] = vd.y; d[2] = vd.z; d[3] = vd.w;
    }
    int pos[4];
#pragma unroll
    for (int j = 0; j < 4; j++) pos[j] = atomicAdd(&g_cursor[d[j]], 1);
#pragma unroll
    for (int j = 0; j < 4; j++) g_csr[pos[j]] = s[j];
}

// ---------------------------------------------------------------------------
// gather-aggregate (mean): one warp per node, 4-way unrolled
__global__ void __launch_bounds__(256) k_agg(const float* __restrict__ feat_param,
                                             int use_h1) {
    int t = blockIdx.x * blockDim.x + threadIdx.x;
    int node = t >> 5;
    if (node >= NN) return;
    int lane = t & 31;
    const float* feat = use_h1 ? g_h1 : feat_param;

    int start = g_rowptr[node];
    int end = start + g_cnt[node];

    float4 a0 = make_float4(0.f, 0.f, 0.f, 0.f);
    float4 a1 = make_float4(0.f, 0.f, 0.f, 0.f);
    float4 a2 = make_float4(0.f, 0.f, 0.f, 0.f);
    float4 a3 = make_float4(0.f, 0.f, 0.f, 0.f);

    int e = start;
    for (; e + 3 < end; e += 4) {
        int s0 = g_csr[e];
        int s1 = g_csr[e + 1];
        int s2 = g_csr[e + 2];
        int s3 = g_csr[e + 3];
        float4 v0 = *((const float4*)(feat + (size_t)s0 * D) + lane);
        float4 v1 = *((const float4*)(feat + (size_t)s1 * D) + lane);
        float4 v2 = *((const float4*)(feat + (size_t)s2 * D) + lane);
        float4 v3 = *((const float4*)(feat + (size_t)s3 * D) + lane);
        a0.x += v0.x; a0.y += v0.y; a0.z += v0.z; a0.w += v0.w;
        a1.x += v1.x; a1.y += v1.y; a1.z += v1.z; a1.w += v1.w;
        a2.x += v2.x; a2.y += v2.y; a2.z += v2.z; a2.w += v2.w;
        a3.x += v3.x; a3.y += v3.y; a3.z += v3.z; a3.w += v3.w;
    }
    for (; e < end; e++) {
        int s0 = g_csr[e];
        float4 v0 = *((const float4*)(feat + (size_t)s0 * D) + lane);
        a0.x += v0.x; a0.y += v0.y; a0.z += v0.z; a0.w += v0.w;
    }

    float di = g_dinv[node];
    float4 r;
    r.x = (a0.x + a1.x + a2.x + a3.x) * di;
    r.y = (a0.y + a1.y + a2.y + a3.y) * di;
    r.z = (a0.z + a1.z + a2.z + a3.z) * di;
    r.w = (a0.w + a1.w + a2.w + a3.w) * di;
    *((float4*)(g_agg + (size_t)node * D) + lane) = r;
}

// ---------------------------------------------------------------------------
// common MMA helpers
__device__ __forceinline__ uint32_t smem_u32(const void* p) {
    uint32_t a;
    asm("{ .reg .u64 t; cvta.to.shared.u64 t, %1; cvt.u32.u64 %0, t; }"
        : "=r"(a) : "l"(p));
    return a;
}

__device__ __forceinline__ void ldm_x4(uint32_t addr, uint32_t* r) {
    asm volatile("ldmatrix.sync.aligned.m8n8.x4.shared.b16 {%0,%1,%2,%3}, [%4];"
                 : "=r"(r[0]), "=r"(r[1]), "=r"(r[2]), "=r"(r[3]) : "r"(addr));
}

__device__ __forceinline__ void mma_bf16(float* d, const uint32_t* a,
                                         const uint32_t* b) {
    asm volatile(
        "mma.sync.aligned.m16n8k16.row.col.f32.bf16.bf16.f32 "
        "{%0,%1,%2,%3}, {%4,%5,%6,%7}, {%8,%9}, {%0,%1,%2,%3};"
        : "+f"(d[0]), "+f"(d[1]), "+f"(d[2]), "+f"(d[3])
        : "r"(a[0]), "r"(a[1]), "r"(a[2]), "r"(a[3]), "r"(b[0]), "r"(b[1]));
}

__device__ __forceinline__ void cvt_pair(float x0, float x1, uint32_t& hi,
                                         uint32_t& lo) {
    __nv_bfloat16 h0 = __float2bfloat16(x0);
    __nv_bfloat16 h1 = __float2bfloat16(x1);
    float r0 = x0 - __bfloat162float(h0);
    float r1 = x1 - __bfloat162float(h1);
    __nv_bfloat162 hp(h0, h1);
    __nv_bfloat162 lp(__float2bfloat16(r0), __float2bfloat16(r1));
    hi = *reinterpret_cast<uint32_t*>(&hp);
    lo = *reinterpret_cast<uint32_t*>(&lp);
}

// ---------------------------------------------------------------------------
// mma.sync bf16 layer, hi/lo split, register-prefetch double buffering.
#define TILES_PER_BLK 3
#define NTILES ((NN + 127) / 128)                               // 391
#define MMA_GRID ((NTILES + TILES_PER_BLK - 1) / TILES_PER_BLK) // 131

#define SB_OFF   0
#define A_HI_OFF 1024
#define A_LO_OFF (A_HI_OFF + 34816)       // 128 rows * 272B
#define B_HI_OFF (A_LO_OFF + 34816)       // 70656
#define B_LO_OFF (B_HI_OFF + 67584)       // 128 rows * 528B
#define SMEM_MMA_BYTES (B_LO_OFF + 67584) // 205824
#define RSA 272
#define RSB 528

#define PREF_A(Asrc, node0_)                                            \
    do {                                                                \
        _Pragma("unroll")                                               \
        for (int i = 0; i < 8; i++) {                                   \
            int p = tid + i * 512;                                      \
            int r = p >> 5;                                             \
            int kq = p & 31;                                            \
            int node = (node0_) + r;                                    \
            pf[i] = (node < NN)                                         \
                ? *(const float4*)((Asrc) + (size_t)node * D + kq * 4)  \
                : make_float4(0.f, 0.f, 0.f, 0.f);                      \
        }                                                               \
    } while (0)

__global__ void __launch_bounds__(512, 1) k_layer_mma(const float* __restrict__ xin_param,
                                                      const float* __restrict__ Wl,
                                                      const float* __restrict__ Wr,
                                                      const float* __restrict__ b,
                                                      int first) {
    extern __shared__ char smem[];
    uint32_t sbase = smem_u32(smem);
    float* sbias = (float*)(smem + SB_OFF);

    const float* xin = first ? xin_param : g_h1;
    float* hout = first ? g_h1 : g_h2;

    int tid = threadIdx.x;
    int lane = tid & 31;
    int wid = tid >> 5;
    int wm = wid >> 2;
    int wn = wid & 3;

    if (tid < 128) sbias[tid] = b[tid];

    float4 pf[8];
    PREF_A(g_agg, blockIdx.x * TILES_PER_BLK * 128);

    for (int i = 0; i < 16; i++) {
        int p = tid + i * 512;
        int o = p >> 6;
        int kq = p & 63;
        float4 v = (kq < 32) ? *(const float4*)(Wl + o * 128 + kq * 4)
                             : *(const float4*)(Wr + o * 128 + (kq - 32) * 4);
        uint32_t h0, l0, h1, l1;
        cvt_pair(v.x, v.y, h0, l0);
        cvt_pair(v.z, v.w, h1, l1);
        *(uint2*)(smem + B_HI_OFF + o * RSB + kq * 8) = make_uint2(h0, h1);
        *(uint2*)(smem + B_LO_OFF + o * RSB + kq * 8) = make_uint2(l0, l1);
    }
    __syncthreads();

    int sub = lane >> 3;
    int rin = lane & 7;
    int a_row = (sub & 1) * 8 + rin;
    int a_kof = (sub >> 1) * 8;
    int b_row = (sub >> 1) * 8 + rin;
    int b_kof = (sub & 1) * 8;

    for (int t = 0; t < TILES_PER_BLK; t++) {
        int node0 = (blockIdx.x * TILES_PER_BLK + t) * 128;
        if (node0 >= NN) break;

        float acc[2][4][4];
#pragma unroll
        for (int mt = 0; mt < 2; mt++)
#pragma unroll
            for (int nt = 0; nt < 4; nt++)
#pragma unroll
                for (int j = 0; j < 4; j++) acc[mt][nt][j] = 0.f;

        for (int half = 0; half < 2; half++) {
#pragma unroll
            for (int i = 0; i < 8; i++) {
                int p = tid + i * 512;
                int r = p >> 5;
                int kq = p & 31;
                uint32_t h0, l0, h1, l1;
                cvt_pair(pf[i].x, pf[i].y, h0, l0);
                cvt_pair(pf[i].z, pf[i].w, h1, l1);
                *(uint2*)(smem + A_HI_OFF + r * RSA + kq * 8) = make_uint2(h0, h1);
                *(uint2*)(smem + A_LO_OFF + r * RSA + kq * 8) = make_uint2(l0, l1);
            }
            __syncthreads();

            if (half == 0) {
                PREF_A(xin, node0);
            } else if (t + 1 < TILES_PER_BLK) {
                PREF_A(g_agg, node0 + 128);
            }

#pragma unroll
            for (int ks = 0; ks < 8; ks++) {
                int akc = ks * 16 + a_kof;
                int bkc = half * 128 + ks * 16 + b_kof;

                uint32_t ah[2][4], al[2][4];
#pragma unroll
                for (int mt = 0; mt < 2; mt++) {
                    uint32_t ro = (uint32_t)((wm * 32 + mt * 16 + a_row) * RSA + akc * 2);
                    ldm_x4(sbase + A_HI_OFF + ro, ah[mt]);
                    ldm_x4(sbase + A_LO_OFF + ro, al[mt]);
                }
                uint32_t bh[2][4], bl[2][4];
#pragma unroll
                for (int np = 0; np < 2; np++) {
                    uint32_t ro = (uint32_t)((wn * 32 + np * 16 + b_row) * RSB + bkc * 2);
                    ldm_x4(sbase + B_HI_OFF + ro, bh[np]);
                    ldm_x4(sbase + B_LO_OFF + ro, bl[np]);
                }
#pragma unroll
                for (int mt = 0; mt < 2; mt++) {
#pragma unroll
                    for (int nt = 0; nt < 4; nt++) {
                        const uint32_t* Bh = &bh[nt >> 1][(nt & 1) * 2];
                        const uint32_t* Bl = &bl[nt >> 1][(nt & 1) * 2];
                        mma_bf16(acc[mt][nt], ah[mt], Bh);
                        mma_bf16(acc[mt][nt], ah[mt], Bl);
                        mma_bf16(acc[mt][nt], al[mt], Bh);
                    }
                }
            }
            __syncthreads();
        }

        int qr = lane >> 2;
        int qc = (lane & 3) * 2;
#pragma unroll
        for (int mt = 0; mt < 2; mt++) {
            int n0 = node0 + wm * 32 + mt * 16 + qr;
            int n1 = n0 + 8;
#pragma unroll
            for (int nt = 0; nt < 4; nt++) {
                int o = wn * 32 + nt * 8 + qc;
                float b0 = sbias[o], b1 = sbias[o + 1];
                if (n0 < NN) {
                    float2 v;
                    v.x = fmaxf(acc[mt][nt][0] + b0, 0.f);
                    v.y = fmaxf(acc[mt][nt][1] + b1, 0.f);
                    *(float2*)(hout + (size_t)n0 * D + o) = v;
                }
                if (n1 < NN) {
                    float2 v;
                    v.x = fmaxf(acc[mt][nt][2] + b0, 0.f);
                    v.y = fmaxf(acc[mt][nt][3] + b1, 0.f);
                    *(float2*)(hout + (size_t)n1 * D + o) = v;
                }
            }
        }
        __syncthreads();
    }
}

// ---------------------------------------------------------------------------
// final head on MMA: 3 tiles per block (reuse converted Wlin, single wave)
#define RSF 528
#define FA_HI 1024
#define FA_LO (FA_HI + 128 * RSF)
#define FB_HI (FA_LO + 128 * RSF)
#define FB_LO (FB_HI + 48 * RSF)
#define SMEM_FIN_BYTES (FB_LO + 48 * RSF)
#define FIN_GRID ((NTILES + 2) / 3)   // 131

__global__ void __launch_bounds__(256, 1) k_final_mma(const float* __restrict__ Wlin,
                                                      const float* __restrict__ blin,
                                                      float* __restrict__ out) {
    extern __shared__ char smem[];
    uint32_t sbase = smem_u32(smem);
    float* sbias = (float*)(smem + SB_OFF);

    int tid = threadIdx.x;
    int lane = tid & 31;
    int wid = tid >> 5;

    if (tid < 48) sbias[tid] = (tid < DOUT) ? blin[tid] : 0.f;

    // Wlin converted once per block
    for (int i = 0; i < 12; i++) {
        int p = tid + i * 256;
        int o = p >> 6;
        int kq = p & 63;
        float4 v = make_float4(0.f, 0.f, 0.f, 0.f);
        if (o < DOUT) v = *(const float4*)(Wlin + o * 256 + kq * 4);
        uint32_t h0, l0, h1, l1;
        cvt_pair(v.x, v.y, h0, l0);
        cvt_pair(v.z, v.w, h1, l1);
        *(uint2*)(smem + FB_HI + o * RSF + kq * 8) = make_uint2(h0, h1);
        *(uint2*)(smem + FB_LO + o * RSF + kq * 8) = make_uint2(l0, l1);
    }

    int sub = lane >> 3;
    int rin = lane & 7;
    int a_row = (sub & 1) * 8 + rin;
    int a_kof = (sub >> 1) * 8;
    int b_row = (sub >> 1) * 8 + rin;
    int b_kof = (sub & 1) * 8;
    int qc = (lane & 3) * 2;
    int qr = lane >> 2;

    for (int t = 0; t < 3; t++) {
        int node0 = (blockIdx.x * 3 + t) * 128;
        if (node0 >= NN) break;
        __syncthreads();   // previous MMA / first-iter W-convert complete

        // A = [h1 | h2] tile
        for (int i = 0; i < 32; i++) {
            int p = tid + i * 256;
            int r = p >> 6;
            int kq = p & 63;
            int node = node0 + r;
            float4 v = make_float4(0.f, 0.f, 0.f, 0.f);
            if (node < NN) {
                const float* src = (kq < 32) ? (g_h1 + (size_t)node * D + kq * 4)
                                             : (g_h2 + (size_t)node * D + (kq - 32) * 4);
                v = *(const float4*)src;
            }
            uint32_t h0, l0, h1, l1;
            cvt_pair(v.x, v.y, h0, l0);
            cvt_pair(v.z, v.w, h1, l1);
            *(uint2*)(smem + FA_HI + r * RSF + kq * 8) = make_uint2(h0, h1);
            *(uint2*)(smem + FA_LO + r * RSF + kq * 8) = make_uint2(l0, l1);
        }
        __syncthreads();

        float acc[5][4];
#pragma unroll
        for (int nt = 0; nt < 5; nt++)
#pragma unroll
            for (int j = 0; j < 4; j++) acc[nt][j] = 0.f;

#pragma unroll
        for (int ks = 0; ks < 16; ks++) {
            uint32_t ah[4], al[4];
            {
                uint32_t ro = (uint32_t)((wid * 16 + a_row) * RSF + (ks * 16 + a_kof) * 2);
                ldm_x4(sbase + FA_HI + ro, ah);
                ldm_x4(sbase + FA_LO + ro, al);
            }
            uint32_t bh[3][4], bl[3][4];
#pragma unroll
            for (int np = 0; np < 3; np++) {
                uint32_t ro = (uint32_t)((np * 16 + b_row) * RSF + (ks * 16 + b_kof) * 2);
                ldm_x4(sbase + FB_HI + ro, bh[np]);
                ldm_x4(sbase + FB_LO + ro, bl[np]);
            }
#pragma unroll
            for (int nt = 0; nt < 5; nt++) {
                const uint32_t* Bh = &bh[nt >> 1][(nt & 1) * 2];
                const uint32_t* Bl = &bl[nt >> 1][(nt & 1) * 2];
                mma_bf16(acc[nt], ah, Bh);
                mma_bf16(acc[nt], ah, Bl);
                mma_bf16(acc[nt], al, Bh);
            }
        }

#pragma unroll
        for (int nt = 0; nt < 5; nt++) {
            int o = nt * 8 + qc;
            acc[nt][0] += sbias[o];
            acc[nt][1] += sbias[o + 1];
            acc[nt][2] += sbias[o];
            acc[nt][3] += sbias[o + 1];
        }

        float m0 = -1e30f, m1 = -1e30f;
#pragma unroll
        for (int nt = 0; nt < 5; nt++) {
            m0 = fmaxf(m0, fmaxf(acc[nt][0], acc[nt][1]));
            m1 = fmaxf(m1, fmaxf(acc[nt][2], acc[nt][3]));
        }
#pragma unroll
        for (int dd = 1; dd <= 2; dd <<= 1) {
            m0 = fmaxf(m0, __shfl_xor_sync(0xffffffffu, m0, dd));
            m1 = fmaxf(m1, __shfl_xor_sync(0xffffffffu, m1, dd));
        }
        float s0 = 0.f, s1 = 0.f;
#pragma unroll
        for (int nt = 0; nt < 5; nt++) {
            s0 += expf(acc[nt][0] - m0) + expf(acc[nt][1] - m0);
            s1 += expf(acc[nt][2] - m1) + expf(acc[nt][3] - m1);
        }
#pragma unroll
        for (int dd = 1; dd <= 2; dd <<= 1) {
            s0 += __shfl_xor_sync(0xffffffffu, s0, dd);
            s1 += __shfl_xor_sync(0xffffffffu, s1, dd);
        }
        float lse0 = m0 + logf(s0);
        float lse1 = m1 + logf(s1);

        int r0 = node0 + wid * 16 + qr;
        int r1 = r0 + 8;
#pragma unroll
        for (int nt = 0; nt < 5; nt++) {
            int o = nt * 8 + qc;
            if (r0 < NN) {
                float2 v = make_float2(acc[nt][0] - lse0, acc[nt][1] - lse0);
                *(float2*)(out + (size_t)r0 * DOUT + o) = v;
            }
            if (r1 < NN) {
                float2 v = make_float2(acc[nt][2] - lse1, acc[nt][3] - lse1);
                *(float2*)(out + (size_t)r1 * DOUT + o) = v;
            }
        }
    }
}

// ---------------------------------------------------------------------------
extern "C" void kernel_launch(void* const* d_in, const int* in_sizes, int n_in,
                              void* d_out, int out_size) {
    const float* x    = (const float*)d_in[0];
    const void*  ei   = d_in[1];
    const float* W1l  = (const float*)d_in[2];
    const float* b1   = (const float*)d_in[3];
    const float* W1r  = (const float*)d_in[4];
    const float* W2l  = (const float*)d_in[5];
    const float* b2   = (const float*)d_in[6];
    const float* W2r  = (const float*)d_in[7];
    const float* Wlin = (const float*)d_in[8];
    const float* blin = (const float*)d_in[9];
    float*       out  = (float*)d_out;

    cudaFuncSetAttribute(k_layer_mma, cudaFuncAttributeMaxDynamicSharedMemorySize,
                         SMEM_MMA_BYTES);
    cudaFuncSetAttribute(k_final_mma, cudaFuncAttributeMaxDynamicSharedMemorySize,
                         SMEM_FIN_BYTES);

    const int quad_blocks = (NE / 4 + 255) / 256;  // 782
    const int agg_blocks  = (NN * 32 + 255) / 256; // 6250

    // CSR build
    k_init<<<NBLK, 256>>>((const int*)ei);
    k_hist<<<quad_blocks, 256>>>(ei);
    k_alloc<<<NBLK, 256>>>();
    k_fill<<<quad_blocks, 256>>>(ei);

    // layer 1
    k_agg<<<agg_blocks, 256>>>(x, 0);
    k_layer_mma<<<MMA_GRID, 512, SMEM_MMA_BYTES>>>(x, W1l, W1r, b1, 1);

    // layer 2
    k_agg<<<agg_blocks, 256>>>(nullptr, 1);
    k_layer_mma<<<MMA_GRID, 512, SMEM_MMA_BYTES>>>(nullptr, W2l, W2r, b2, 0);

    // head
    k_final_mma<<<FIN_GRID, 256, SMEM_FIN_BYTES>>>(Wlin, blin, out);
}